// round 3
// baseline (speedup 1.0000x reference)
#include <cuda_runtime.h>

#define NT 256          // threads per block
#define TS 64           // tile size (rows)
#define LDA 68          // sA row stride (floats)

typedef unsigned long long u64;

__device__ float g_h [50048 * 64];
__device__ float g_x [50048 * 3];
__device__ float g_Ad[50048 * 64];   // h @ e_w1[0:64]   (dst part)
__device__ float g_As[50048 * 64];   // h @ e_w1[64:128] (src part)
__device__ float g_m [50048 * 64];   // segment-sum of m_ij
__device__ float g_dx[50048 * 3];    // segment-sum of W_ij * x_diff

__device__ __forceinline__ float silu_f(float v) {
    return v / (1.0f + __expf(-v));
}
__device__ __forceinline__ u64 pdup(float x) {
    u64 r; asm("mov.b64 %0, {%1, %1};" : "=l"(r) : "f"(x)); return r;
}
__device__ __forceinline__ void up2(u64 v, float& a, float& b) {
    asm("mov.b64 {%0, %1}, %2;" : "=f"(a), "=f"(b) : "l"(v));
}
__device__ __forceinline__ void fma2(u64& c, u64 a, u64 b) {
    asm("fma.rn.f32x2 %0, %1, %2, %0;" : "+l"(c) : "l"(a), "l"(b));
}

// 64x64 tile GEMM via packed f32x2 FMA, 256 threads.
// tx = tid&7  -> cols tx*8..tx*8+7 (4 f32x2 pairs)
// ty = tid>>3 -> rows ty*2, ty*2+1
__device__ __forceinline__ void gemm_t(const float* __restrict__ sA,
                                       const float* __restrict__ sW,
                                       int tx, int ty, u64 acc[2][4]) {
    const float* aR = sA + ty * 2 * LDA;
    const float* bC = sW + tx * 8;
#pragma unroll
    for (int kb = 0; kb < 64; kb += 4) {
        float4 av0 = *(const float4*)(aR + kb);
        float4 av1 = *(const float4*)(aR + LDA + kb);
#pragma unroll
        for (int kk = 0; kk < 4; kk++) {
            ulonglong2 b0 = *(const ulonglong2*)(bC + (kb + kk) * 64);
            ulonglong2 b1 = *(const ulonglong2*)(bC + (kb + kk) * 64 + 4);
            float a0 = (kk == 0) ? av0.x : (kk == 1) ? av0.y : (kk == 2) ? av0.z : av0.w;
            float a1 = (kk == 0) ? av1.x : (kk == 1) ? av1.y : (kk == 2) ? av1.z : av1.w;
            u64 p0 = pdup(a0), p1 = pdup(a1);
            fma2(acc[0][0], p0, b0.x);
            fma2(acc[0][1], p0, b0.y);
            fma2(acc[0][2], p0, b1.x);
            fma2(acc[0][3], p0, b1.y);
            fma2(acc[1][0], p1, b0.x);
            fma2(acc[1][1], p1, b0.y);
            fma2(acc[1][2], p1, b1.x);
            fma2(acc[1][3], p1, b1.y);
        }
    }
}

#define ZERO_ACC(acc)                             \
    _Pragma("unroll") for (int i = 0; i < 2; i++) \
    _Pragma("unroll") for (int j = 0; j < 4; j++) (acc)[i][j] = 0ull;

// unpack a row of 4 f32x2 accumulators into c[8]
#define UNPACK_ROW(acc_row, c)                    \
    _Pragma("unroll") for (int p_ = 0; p_ < 4; p_++) up2((acc_row)[p_], (c)[2 * p_], (c)[2 * p_ + 1]);

// ---------------------------------------------------------------------------
__global__ void init_kernel(const int* __restrict__ an,
                            const float* __restrict__ pos,
                            const float* __restrict__ emb, int N) {
    int p = blockIdx.x * blockDim.x + threadIdx.x;
    int nh = N * 64;
    if (p < nh) {
        int n = p >> 6, j = p & 63;
        g_h[p] = emb[an[n] * 64 + j];
    } else if (p < nh + N * 3) {
        g_x[p - nh] = pos[p - nh];
    }
}

// ---------------------------------------------------------------------------
// Per-layer node precompute: Ad = h@W1[0:64], As = h@W1[64:128].
// Also zeroes this layer's m / dx accumulators.
__global__ __launch_bounds__(NT)
void node_pre_kernel(const float* __restrict__ w1, int N) {
    __shared__ float sA[TS * LDA];
    __shared__ float sW[4096];
    int tid = threadIdx.x;
    int n0 = blockIdx.x * TS;
    int tx = tid & 7, ty = tid >> 3;

    for (int p = tid; p < TS * 16; p += NT) {
        int i = p >> 4, j = (p & 15) * 4;
        int n = n0 + i;
        float4 v = make_float4(0.f, 0.f, 0.f, 0.f);
        if (n < N) {
            v = *(const float4*)&g_h[n * 64 + j];
            *(float4*)&g_m[n * 64 + j] = make_float4(0.f, 0.f, 0.f, 0.f);
        }
        *(float4*)&sA[i * LDA + j] = v;
    }
    if (tid < TS * 3) {
        int idx = n0 * 3 + tid;
        if (idx < N * 3) g_dx[idx] = 0.f;
    }
    for (int p = tid; p < 1024; p += NT)
        *(float4*)&sW[p * 4] = *(const float4*)&w1[p * 4];
    __syncthreads();

    u64 acc[2][4];
    ZERO_ACC(acc);
    gemm_t(sA, sW, tx, ty, acc);

#pragma unroll
    for (int i = 0; i < 2; i++) {
        int n = n0 + ty * 2 + i;
        if (n < N) {
            float c[8];
            UNPACK_ROW(acc[i], c);
            *(float4*)&g_Ad[n * 64 + tx * 8]     = make_float4(c[0], c[1], c[2], c[3]);
            *(float4*)&g_Ad[n * 64 + tx * 8 + 4] = make_float4(c[4], c[5], c[6], c[7]);
        }
    }
    __syncthreads();
    for (int p = tid; p < 1024; p += NT)
        *(float4*)&sW[p * 4] = *(const float4*)&w1[4096 + p * 4];
    __syncthreads();

    ZERO_ACC(acc);
    gemm_t(sA, sW, tx, ty, acc);

#pragma unroll
    for (int i = 0; i < 2; i++) {
        int n = n0 + ty * 2 + i;
        if (n < N) {
            float c[8];
            UNPACK_ROW(acc[i], c);
            *(float4*)&g_As[n * 64 + tx * 8]     = make_float4(c[0], c[1], c[2], c[3]);
            *(float4*)&g_As[n * 64 + tx * 8 + 4] = make_float4(c[4], c[5], c[6], c[7]);
        }
    }
}

// ---------------------------------------------------------------------------
// Edge kernel: t1 = silu(Ad[dst]+As[src]+r*w1r+b1); m = silu(t1@w2+b2);
// scatter m -> g_m[dst]; u = silu(m@xw1+xb1); W = u.xw2+xb2;
// scatter W*x_diff -> g_dx[dst].
__global__ __launch_bounds__(NT)
void edge_kernel(const int* __restrict__ src, const int* __restrict__ dst,
                 const float* __restrict__ w1r, const float* __restrict__ b1,
                 const float* __restrict__ w2,  const float* __restrict__ b2,
                 const float* __restrict__ xw1, const float* __restrict__ xb1,
                 const float* __restrict__ xw2, const float* __restrict__ xb2,
                 int E) {
    __shared__ float sA[TS * LDA];
    __shared__ float sW[4096];
    __shared__ float sxd[TS * 3];
    __shared__ float sr[TS];
    __shared__ float sWe[TS];
    __shared__ int   sdst[TS];
    __shared__ int   ssrc[TS];
    __shared__ float sw1r[64], sb1[64], sb2[64], sxb1[64], sxw2[64];

    int tid = threadIdx.x;
    int e0  = blockIdx.x * TS;
    int tx = tid & 7, ty = tid >> 3;

    if (tid < TS) {
        int eg = e0 + tid;
        if (eg < E) {
            int s = src[eg], d = dst[eg];
            ssrc[tid] = s; sdst[tid] = d;
            float d0 = g_x[s * 3 + 0] - g_x[d * 3 + 0];
            float d1 = g_x[s * 3 + 1] - g_x[d * 3 + 1];
            float d2 = g_x[s * 3 + 2] - g_x[d * 3 + 2];
            sxd[tid * 3 + 0] = d0; sxd[tid * 3 + 1] = d1; sxd[tid * 3 + 2] = d2;
            sr[tid] = sqrtf(d0 * d0 + d1 * d1 + d2 * d2);
        } else {
            ssrc[tid] = 0; sdst[tid] = -1;
            sxd[tid * 3 + 0] = 0.f; sxd[tid * 3 + 1] = 0.f; sxd[tid * 3 + 2] = 0.f;
            sr[tid] = 0.f;
        }
    }
    if (tid >= 64 && tid < 128) {
        int j = tid - 64;
        sw1r[j] = w1r[j]; sb1[j] = b1[j]; sb2[j] = b2[j];
        sxb1[j] = xb1[j]; sxw2[j] = xw2[j];
    }
    for (int p = tid; p < 1024; p += NT)
        *(float4*)&sW[p * 4] = *(const float4*)&w2[p * 4];
    __syncthreads();

    // stage 1: t1 (vectorized gather from node-level precomputed products)
    for (int p = tid; p < TS * 16; p += NT) {
        int e = p >> 4, j = (p & 15) * 4;
        int d = sdst[e];
        int dd = d < 0 ? 0 : d;
        int s  = ssrc[e];
        float4 ad = *(const float4*)&g_Ad[dd * 64 + j];
        float4 as = *(const float4*)&g_As[s * 64 + j];
        float r = sr[e];
        float4 o;
        o.x = silu_f(ad.x + as.x + r * sw1r[j + 0] + sb1[j + 0]);
        o.y = silu_f(ad.y + as.y + r * sw1r[j + 1] + sb1[j + 1]);
        o.z = silu_f(ad.z + as.z + r * sw1r[j + 2] + sb1[j + 2]);
        o.w = silu_f(ad.w + as.w + r * sw1r[j + 3] + sb1[j + 3]);
        *(float4*)&sA[e * LDA + j] = o;
    }
    __syncthreads();

    u64 acc[2][4];
    ZERO_ACC(acc);
    gemm_t(sA, sW, tx, ty, acc);
    __syncthreads();   // all reads of sA/sW done

    // m = silu(acc + b2) -> sA; scatter to g_m; then load xw1
#pragma unroll
    for (int i = 0; i < 2; i++) {
        int e = ty * 2 + i;
        int d = sdst[e];
        float c[8];
        UNPACK_ROW(acc[i], c);
#pragma unroll
        for (int q = 0; q < 8; q++) c[q] = silu_f(c[q] + sb2[tx * 8 + q]);
        *(float4*)&sA[e * LDA + tx * 8]     = make_float4(c[0], c[1], c[2], c[3]);
        *(float4*)&sA[e * LDA + tx * 8 + 4] = make_float4(c[4], c[5], c[6], c[7]);
        if (d >= 0) {
#pragma unroll
            for (int q = 0; q < 8; q++)
                atomicAdd(&g_m[d * 64 + tx * 8 + q], c[q]);
        }
    }
    for (int p = tid; p < 1024; p += NT)
        *(float4*)&sW[p * 4] = *(const float4*)&xw1[p * 4];
    __syncthreads();

    ZERO_ACC(acc);
    gemm_t(sA, sW, tx, ty, acc);

    // u = silu(acc + xb1); partial W = u . xw2; reduce over 8 tx lanes
    float part[2];
#pragma unroll
    for (int i = 0; i < 2; i++) {
        float c[8];
        UNPACK_ROW(acc[i], c);
        float pp = 0.f;
#pragma unroll
        for (int q = 0; q < 8; q++)
            pp += silu_f(c[q] + sxb1[tx * 8 + q]) * sxw2[tx * 8 + q];
        part[i] = pp;
    }
#pragma unroll
    for (int off = 4; off >= 1; off >>= 1)
#pragma unroll
        for (int i = 0; i < 2; i++)
            part[i] += __shfl_xor_sync(0xffffffffu, part[i], off);
    if (tx == 0) {
        float xb2v = __ldg(xb2);
        sWe[ty * 2 + 0] = part[0] + xb2v;
        sWe[ty * 2 + 1] = part[1] + xb2v;
    }
    __syncthreads();

    if (tid < TS * 3) {
        int e = tid / 3, cc = tid - e * 3;
        int d = sdst[e];
        if (d >= 0) atomicAdd(&g_dx[d * 3 + cc], sWe[e] * sxd[e * 3 + cc]);
    }
}

// ---------------------------------------------------------------------------
// Node update: h += silu([h,m]@h_w1 + b1) @ h_w2 + b2 ; x += dx
// If outh != nullptr, final layer: write results to output instead of g_h/g_x.
__global__ __launch_bounds__(NT)
void node_update_kernel(const float* __restrict__ hw1, const float* __restrict__ hb1,
                        const float* __restrict__ hw2, const float* __restrict__ hb2,
                        float* __restrict__ outh, float* __restrict__ outx, int N) {
    __shared__ float sA[TS * LDA];
    __shared__ float sW[4096];
    int tid = threadIdx.x;
    int n0 = blockIdx.x * TS;
    int tx = tid & 7, ty = tid >> 3;

    // pass A: h part
    for (int p = tid; p < TS * 16; p += NT) {
        int i = p >> 4, j = (p & 15) * 4;
        int n = n0 + i;
        float4 v = make_float4(0.f, 0.f, 0.f, 0.f);
        if (n < N) v = *(const float4*)&g_h[n * 64 + j];
        *(float4*)&sA[i * LDA + j] = v;
    }
    for (int p = tid; p < 1024; p += NT)
        *(float4*)&sW[p * 4] = *(const float4*)&hw1[p * 4];
    __syncthreads();

    u64 acc[2][4];
    ZERO_ACC(acc);
    gemm_t(sA, sW, tx, ty, acc);
    __syncthreads();

    // pass B: m part (accumulate into same acc)
    for (int p = tid; p < TS * 16; p += NT) {
        int i = p >> 4, j = (p & 15) * 4;
        int n = n0 + i;
        float4 v = make_float4(0.f, 0.f, 0.f, 0.f);
        if (n < N) v = *(const float4*)&g_m[n * 64 + j];
        *(float4*)&sA[i * LDA + j] = v;
    }
    for (int p = tid; p < 1024; p += NT)
        *(float4*)&sW[p * 4] = *(const float4*)&hw1[4096 + p * 4];
    __syncthreads();
    gemm_t(sA, sW, tx, ty, acc);
    __syncthreads();

    // t = silu(acc + hb1) -> sA ; load h_w2
#pragma unroll
    for (int i = 0; i < 2; i++) {
        int e = ty * 2 + i;
        float c[8];
        UNPACK_ROW(acc[i], c);
#pragma unroll
        for (int q = 0; q < 8; q++) c[q] = silu_f(c[q] + hb1[tx * 8 + q]);
        *(float4*)&sA[e * LDA + tx * 8]     = make_float4(c[0], c[1], c[2], c[3]);
        *(float4*)&sA[e * LDA + tx * 8 + 4] = make_float4(c[4], c[5], c[6], c[7]);
    }
    for (int p = tid; p < 1024; p += NT)
        *(float4*)&sW[p * 4] = *(const float4*)&hw2[p * 4];
    __syncthreads();

    ZERO_ACC(acc);
    gemm_t(sA, sW, tx, ty, acc);

    float* hdst = outh ? outh : g_h;
#pragma unroll
    for (int i = 0; i < 2; i++) {
        int n = n0 + ty * 2 + i;
        if (n < N) {
            float c[8];
            UNPACK_ROW(acc[i], c);
            float4 o0 = *(const float4*)&g_h[n * 64 + tx * 8];
            float4 o1 = *(const float4*)&g_h[n * 64 + tx * 8 + 4];
            o0.x += c[0] + hb2[tx * 8 + 0]; o0.y += c[1] + hb2[tx * 8 + 1];
            o0.z += c[2] + hb2[tx * 8 + 2]; o0.w += c[3] + hb2[tx * 8 + 3];
            o1.x += c[4] + hb2[tx * 8 + 4]; o1.y += c[5] + hb2[tx * 8 + 5];
            o1.z += c[6] + hb2[tx * 8 + 6]; o1.w += c[7] + hb2[tx * 8 + 7];
            *(float4*)&hdst[n * 64 + tx * 8]     = o0;
            *(float4*)&hdst[n * 64 + tx * 8 + 4] = o1;
        }
    }
    float* xdst = outx ? outx : g_x;
    if (tid < TS * 3) {
        int idx = n0 * 3 + tid;
        if (idx < N * 3) xdst[idx] = g_x[idx] + g_dx[idx];
    }
}

// ---------------------------------------------------------------------------
extern "C" void kernel_launch(void* const* d_in, const int* in_sizes, int n_in,
                              void* d_out, int out_size) {
    const int*   an   = (const int*)d_in[0];
    const float* pos  = (const float*)d_in[1];
    const int*   eidx = (const int*)d_in[2];
    // d_in[3] = edge_attr (unused by reference)
    const float* emb  = (const float*)d_in[4];
    const float* e_w1 = (const float*)d_in[5];
    const float* e_b1 = (const float*)d_in[6];
    const float* e_w2 = (const float*)d_in[7];
    const float* e_b2 = (const float*)d_in[8];
    const float* h_w1 = (const float*)d_in[9];
    const float* h_b1 = (const float*)d_in[10];
    const float* h_w2 = (const float*)d_in[11];
    const float* h_b2 = (const float*)d_in[12];
    const float* x_w1 = (const float*)d_in[13];
    const float* x_b1 = (const float*)d_in[14];
    const float* x_w2 = (const float*)d_in[15];
    const float* x_b2 = (const float*)d_in[16];

    int N = in_sizes[0];
    int E = in_sizes[2] / 2;
    float* out = (float*)d_out;

    int nodeBlocks = (N + TS - 1) / TS;
    int edgeBlocks = (E + TS - 1) / TS;
    int totBlocks  = (N * 67 + 255) / 256;

    init_kernel<<<totBlocks, 256>>>(an, pos, emb, N);

    for (int l = 0; l < 2; l++) {
        const float* ew1l = e_w1 + l * 129 * 64;
        node_pre_kernel<<<nodeBlocks, NT>>>(ew1l, N);
        edge_kernel<<<edgeBlocks, NT>>>(
            eidx, eidx + E,
            ew1l + 128 * 64, e_b1 + l * 64,
            e_w2 + l * 4096, e_b2 + l * 64,
            x_w1 + l * 4096, x_b1 + l * 64,
            x_w2 + l * 64, x_b2 + l,
            E);
        bool last = (l == 1);
        node_update_kernel<<<nodeBlocks, NT>>>(
            h_w1 + l * 128 * 64, h_b1 + l * 64,
            h_w2 + l * 4096, h_b2 + l * 64,
            last ? out : nullptr, last ? out + (size_t)N * 64 : nullptr, N);
    }
}

// round 4
// speedup vs baseline: 2.2996x; 2.2996x over previous
#include <cuda_runtime.h>

#define NT 256          // threads per block
#define TS 64           // tile size (rows)
#define LDA 68          // sA row stride (floats)

typedef unsigned long long u64;

__device__ float g_h [50048 * 64];
__device__ float g_x [50048 * 3];
__device__ float g_Ad[50048 * 64];   // h @ e_w1[0:64]   (dst part)
__device__ float g_As[50048 * 64];   // h @ e_w1[64:128] (src part)
__device__ float g_m [50048 * 64];   // segment-sum of m_ij
__device__ float g_dx[50048 * 3];    // segment-sum of W_ij * x_diff

__device__ __forceinline__ float silu_f(float v) {
    return v / (1.0f + __expf(-v));
}
__device__ __forceinline__ u64 pdup(float x) {
    u64 r; asm("mov.b64 %0, {%1, %1};" : "=l"(r) : "f"(x)); return r;
}
__device__ __forceinline__ void up2(u64 v, float& a, float& b) {
    asm("mov.b64 {%0, %1}, %2;" : "=f"(a), "=f"(b) : "l"(v));
}
__device__ __forceinline__ void fma2(u64& c, u64 a, u64 b) {
    asm("fma.rn.f32x2 %0, %1, %2, %0;" : "+l"(c) : "l"(a), "l"(b));
}
__device__ __forceinline__ void red_add_v4(float* p, float a, float b, float c, float d) {
    asm volatile("red.global.add.v4.f32 [%0], {%1, %2, %3, %4};"
                 :: "l"(p), "f"(a), "f"(b), "f"(c), "f"(d) : "memory");
}

// 64x64 tile GEMM: 256 threads, microtile 4 rows x 4 cols (2 f32x2 accs/row).
// tx = tid&15 -> cols tx*4..tx*4+3; ty = tid>>4 -> rows ty*4..ty*4+3.
__device__ __forceinline__ void gemm_t(const float* __restrict__ sA,
                                       const float* __restrict__ sW,
                                       int tx, int ty, u64 acc[4][2]) {
    const float* aR = sA + ty * 4 * LDA;
    const float* bC = sW + tx * 4;
#pragma unroll
    for (int kb = 0; kb < 64; kb += 4) {
        float4 av[4];
#pragma unroll
        for (int i = 0; i < 4; i++)
            av[i] = *(const float4*)(aR + i * LDA + kb);
#pragma unroll
        for (int kk = 0; kk < 4; kk++) {
            ulonglong2 b = *(const ulonglong2*)(bC + (kb + kk) * 64);
#pragma unroll
            for (int i = 0; i < 4; i++) {
                float a = (kk == 0) ? av[i].x : (kk == 1) ? av[i].y
                        : (kk == 2) ? av[i].z : av[i].w;
                u64 aa = pdup(a);
                fma2(acc[i][0], aa, b.x);
                fma2(acc[i][1], aa, b.y);
            }
        }
    }
}

#define ZERO_ACC(acc)                             \
    _Pragma("unroll") for (int i_ = 0; i_ < 4; i_++) { (acc)[i_][0] = 0ull; (acc)[i_][1] = 0ull; }

#define UNPACK_ROW(acc_row, c)  \
    up2((acc_row)[0], (c)[0], (c)[1]); up2((acc_row)[1], (c)[2], (c)[3]);

// ---------------------------------------------------------------------------
__global__ void init_kernel(const int* __restrict__ an,
                            const float* __restrict__ pos,
                            const float* __restrict__ emb, int N) {
    int p = blockIdx.x * blockDim.x + threadIdx.x;
    int nh = N * 64;
    if (p < nh) {
        int n = p >> 6, j = p & 63;
        g_h[p] = emb[an[n] * 64 + j];
    } else if (p < nh + N * 3) {
        g_x[p - nh] = pos[p - nh];
    }
}

// ---------------------------------------------------------------------------
// Per-layer node precompute: Ad = h@W1[0:64], As = h@W1[64:128].
// Also zeroes this layer's m / dx accumulators.
__global__ __launch_bounds__(NT)
void node_pre_kernel(const float* __restrict__ w1, int N) {
    __shared__ float sA[TS * LDA];
    __shared__ float sW[4096];
    int tid = threadIdx.x;
    int n0 = blockIdx.x * TS;
    int tx = tid & 15, ty = tid >> 4;

    for (int p = tid; p < TS * 16; p += NT) {
        int i = p >> 4, j = (p & 15) * 4;
        int n = n0 + i;
        float4 v = make_float4(0.f, 0.f, 0.f, 0.f);
        if (n < N) {
            v = *(const float4*)&g_h[n * 64 + j];
            *(float4*)&g_m[n * 64 + j] = make_float4(0.f, 0.f, 0.f, 0.f);
        }
        *(float4*)&sA[i * LDA + j] = v;
    }
    if (tid < TS * 3) {
        int idx = n0 * 3 + tid;
        if (idx < N * 3) g_dx[idx] = 0.f;
    }
    for (int p = tid; p < 1024; p += NT)
        *(float4*)&sW[p * 4] = *(const float4*)&w1[p * 4];
    __syncthreads();

    u64 acc[4][2];
    ZERO_ACC(acc);
    gemm_t(sA, sW, tx, ty, acc);

#pragma unroll
    for (int i = 0; i < 4; i++) {
        int n = n0 + ty * 4 + i;
        if (n < N) {
            float c[4];
            UNPACK_ROW(acc[i], c);
            *(float4*)&g_Ad[n * 64 + tx * 4] = make_float4(c[0], c[1], c[2], c[3]);
        }
    }
    __syncthreads();
    for (int p = tid; p < 1024; p += NT)
        *(float4*)&sW[p * 4] = *(const float4*)&w1[4096 + p * 4];
    __syncthreads();

    ZERO_ACC(acc);
    gemm_t(sA, sW, tx, ty, acc);

#pragma unroll
    for (int i = 0; i < 4; i++) {
        int n = n0 + ty * 4 + i;
        if (n < N) {
            float c[4];
            UNPACK_ROW(acc[i], c);
            *(float4*)&g_As[n * 64 + tx * 4] = make_float4(c[0], c[1], c[2], c[3]);
        }
    }
}

// ---------------------------------------------------------------------------
// Edge kernel: t1 = silu(Ad[dst]+As[src]+r*w1r+b1); m = silu(t1@w2+b2);
// scatter m -> g_m[dst]; u = silu(m@xw1+xb1); W = u.xw2+xb2;
// scatter W*x_diff -> g_dx[dst].
__global__ __launch_bounds__(NT)
void edge_kernel(const int* __restrict__ src, const int* __restrict__ dst,
                 const float* __restrict__ w1r, const float* __restrict__ b1,
                 const float* __restrict__ w2,  const float* __restrict__ b2,
                 const float* __restrict__ xw1, const float* __restrict__ xb1,
                 const float* __restrict__ xw2, const float* __restrict__ xb2,
                 int E) {
    __shared__ float sA[TS * LDA];
    __shared__ float sW[4096];
    __shared__ float sxd[TS * 3];
    __shared__ float sr[TS];
    __shared__ float sWe[TS];
    __shared__ int   sdst[TS];
    __shared__ int   ssrc[TS];
    __shared__ float sw1r[64], sb1[64], sb2[64], sxb1[64], sxw2[64];

    int tid = threadIdx.x;
    int e0  = blockIdx.x * TS;
    int tx = tid & 15, ty = tid >> 4;

    if (tid < TS) {
        int eg = e0 + tid;
        if (eg < E) {
            int s = src[eg], d = dst[eg];
            ssrc[tid] = s; sdst[tid] = d;
            float d0 = g_x[s * 3 + 0] - g_x[d * 3 + 0];
            float d1 = g_x[s * 3 + 1] - g_x[d * 3 + 1];
            float d2 = g_x[s * 3 + 2] - g_x[d * 3 + 2];
            sxd[tid * 3 + 0] = d0; sxd[tid * 3 + 1] = d1; sxd[tid * 3 + 2] = d2;
            sr[tid] = sqrtf(d0 * d0 + d1 * d1 + d2 * d2);
        } else {
            ssrc[tid] = 0; sdst[tid] = -1;
            sxd[tid * 3 + 0] = 0.f; sxd[tid * 3 + 1] = 0.f; sxd[tid * 3 + 2] = 0.f;
            sr[tid] = 0.f;
        }
    }
    if (tid >= 64 && tid < 128) {
        int j = tid - 64;
        sw1r[j] = w1r[j]; sb1[j] = b1[j]; sb2[j] = b2[j];
        sxb1[j] = xb1[j]; sxw2[j] = xw2[j];
    }
    for (int p = tid; p < 1024; p += NT)
        *(float4*)&sW[p * 4] = *(const float4*)&w2[p * 4];
    __syncthreads();

    // stage 1: t1 (vectorized gather from node-level precomputed products)
    for (int p = tid; p < TS * 16; p += NT) {
        int e = p >> 4, j = (p & 15) * 4;
        int d = sdst[e];
        int dd = d < 0 ? 0 : d;
        int s  = ssrc[e];
        float4 ad = *(const float4*)&g_Ad[dd * 64 + j];
        float4 as = *(const float4*)&g_As[s * 64 + j];
        float r = sr[e];
        float4 o;
        o.x = silu_f(ad.x + as.x + r * sw1r[j + 0] + sb1[j + 0]);
        o.y = silu_f(ad.y + as.y + r * sw1r[j + 1] + sb1[j + 1]);
        o.z = silu_f(ad.z + as.z + r * sw1r[j + 2] + sb1[j + 2]);
        o.w = silu_f(ad.w + as.w + r * sw1r[j + 3] + sb1[j + 3]);
        *(float4*)&sA[e * LDA + j] = o;
    }
    __syncthreads();

    u64 acc[4][2];
    ZERO_ACC(acc);
    gemm_t(sA, sW, tx, ty, acc);
    __syncthreads();   // all reads of sA/sW done

    // m = silu(acc + b2) -> sA; vectored reduction to g_m; then load xw1
#pragma unroll
    for (int i = 0; i < 4; i++) {
        int e = ty * 4 + i;
        int d = sdst[e];
        float c[4];
        UNPACK_ROW(acc[i], c);
#pragma unroll
        for (int q = 0; q < 4; q++) c[q] = silu_f(c[q] + sb2[tx * 4 + q]);
        *(float4*)&sA[e * LDA + tx * 4] = make_float4(c[0], c[1], c[2], c[3]);
        if (d >= 0)
            red_add_v4(&g_m[d * 64 + tx * 4], c[0], c[1], c[2], c[3]);
    }
    for (int p = tid; p < 1024; p += NT)
        *(float4*)&sW[p * 4] = *(const float4*)&xw1[p * 4];
    __syncthreads();

    ZERO_ACC(acc);
    gemm_t(sA, sW, tx, ty, acc);

    // u = silu(acc + xb1); partial W = u . xw2; reduce over 16 tx lanes
    float part[4];
#pragma unroll
    for (int i = 0; i < 4; i++) {
        float c[4];
        UNPACK_ROW(acc[i], c);
        float pp = 0.f;
#pragma unroll
        for (int q = 0; q < 4; q++)
            pp += silu_f(c[q] + sxb1[tx * 4 + q]) * sxw2[tx * 4 + q];
        part[i] = pp;
    }
#pragma unroll
    for (int off = 8; off >= 1; off >>= 1)
#pragma unroll
        for (int i = 0; i < 4; i++)
            part[i] += __shfl_xor_sync(0xffffffffu, part[i], off);
    if (tx == 0) {
        float xb2v = __ldg(xb2);
#pragma unroll
        for (int i = 0; i < 4; i++) sWe[ty * 4 + i] = part[i] + xb2v;
    }
    __syncthreads();

    if (tid < TS * 3) {
        int e = tid / 3, cc = tid - e * 3;
        int d = sdst[e];
        if (d >= 0) atomicAdd(&g_dx[d * 3 + cc], sWe[e] * sxd[e * 3 + cc]);
    }
}

// ---------------------------------------------------------------------------
// Node update: h += silu([h,m]@h_w1 + b1) @ h_w2 + b2 ; x += dx
// If outh != nullptr, final layer: write results to output instead of g_h/g_x.
__global__ __launch_bounds__(NT)
void node_update_kernel(const float* __restrict__ hw1, const float* __restrict__ hb1,
                        const float* __restrict__ hw2, const float* __restrict__ hb2,
                        float* __restrict__ outh, float* __restrict__ outx, int N) {
    __shared__ float sA[TS * LDA];
    __shared__ float sW[4096];
    int tid = threadIdx.x;
    int n0 = blockIdx.x * TS;
    int tx = tid & 15, ty = tid >> 4;

    // pass A: h part
    for (int p = tid; p < TS * 16; p += NT) {
        int i = p >> 4, j = (p & 15) * 4;
        int n = n0 + i;
        float4 v = make_float4(0.f, 0.f, 0.f, 0.f);
        if (n < N) v = *(const float4*)&g_h[n * 64 + j];
        *(float4*)&sA[i * LDA + j] = v;
    }
    for (int p = tid; p < 1024; p += NT)
        *(float4*)&sW[p * 4] = *(const float4*)&hw1[p * 4];
    __syncthreads();

    u64 acc[4][2];
    ZERO_ACC(acc);
    gemm_t(sA, sW, tx, ty, acc);
    __syncthreads();

    // pass B: m part (accumulate into same acc)
    for (int p = tid; p < TS * 16; p += NT) {
        int i = p >> 4, j = (p & 15) * 4;
        int n = n0 + i;
        float4 v = make_float4(0.f, 0.f, 0.f, 0.f);
        if (n < N) v = *(const float4*)&g_m[n * 64 + j];
        *(float4*)&sA[i * LDA + j] = v;
    }
    for (int p = tid; p < 1024; p += NT)
        *(float4*)&sW[p * 4] = *(const float4*)&hw1[4096 + p * 4];
    __syncthreads();
    gemm_t(sA, sW, tx, ty, acc);
    __syncthreads();

    // t = silu(acc + hb1) -> sA ; load h_w2
#pragma unroll
    for (int i = 0; i < 4; i++) {
        int e = ty * 4 + i;
        float c[4];
        UNPACK_ROW(acc[i], c);
#pragma unroll
        for (int q = 0; q < 4; q++) c[q] = silu_f(c[q] + hb1[tx * 4 + q]);
        *(float4*)&sA[e * LDA + tx * 4] = make_float4(c[0], c[1], c[2], c[3]);
    }
    for (int p = tid; p < 1024; p += NT)
        *(float4*)&sW[p * 4] = *(const float4*)&hw2[p * 4];
    __syncthreads();

    ZERO_ACC(acc);
    gemm_t(sA, sW, tx, ty, acc);

    float* hdst = outh ? outh : g_h;
#pragma unroll
    for (int i = 0; i < 4; i++) {
        int n = n0 + ty * 4 + i;
        if (n < N) {
            float c[4];
            UNPACK_ROW(acc[i], c);
            float4 o = *(const float4*)&g_h[n * 64 + tx * 4];
            o.x += c[0] + hb2[tx * 4 + 0];
            o.y += c[1] + hb2[tx * 4 + 1];
            o.z += c[2] + hb2[tx * 4 + 2];
            o.w += c[3] + hb2[tx * 4 + 3];
            *(float4*)&hdst[n * 64 + tx * 4] = o;
        }
    }
    float* xdst = outx ? outx : g_x;
    if (tid < TS * 3) {
        int idx = n0 * 3 + tid;
        if (idx < N * 3) xdst[idx] = g_x[idx] + g_dx[idx];
    }
}

// ---------------------------------------------------------------------------
extern "C" void kernel_launch(void* const* d_in, const int* in_sizes, int n_in,
                              void* d_out, int out_size) {
    const int*   an   = (const int*)d_in[0];
    const float* pos  = (const float*)d_in[1];
    const int*   eidx = (const int*)d_in[2];
    // d_in[3] = edge_attr (unused by reference)
    const float* emb  = (const float*)d_in[4];
    const float* e_w1 = (const float*)d_in[5];
    const float* e_b1 = (const float*)d_in[6];
    const float* e_w2 = (const float*)d_in[7];
    const float* e_b2 = (const float*)d_in[8];
    const float* h_w1 = (const float*)d_in[9];
    const float* h_b1 = (const float*)d_in[10];
    const float* h_w2 = (const float*)d_in[11];
    const float* h_b2 = (const float*)d_in[12];
    const float* x_w1 = (const float*)d_in[13];
    const float* x_b1 = (const float*)d_in[14];
    const float* x_w2 = (const float*)d_in[15];
    const float* x_b2 = (const float*)d_in[16];

    int N = in_sizes[0];
    int E = in_sizes[2] / 2;
    float* out = (float*)d_out;

    int nodeBlocks = (N + TS - 1) / TS;
    int edgeBlocks = (E + TS - 1) / TS;
    int totBlocks  = (N * 67 + 255) / 256;

    init_kernel<<<totBlocks, 256>>>(an, pos, emb, N);

    for (int l = 0; l < 2; l++) {
        const float* ew1l = e_w1 + l * 129 * 64;
        node_pre_kernel<<<nodeBlocks, NT>>>(ew1l, N);
        edge_kernel<<<edgeBlocks, NT>>>(
            eidx, eidx + E,
            ew1l + 128 * 64, e_b1 + l * 64,
            e_w2 + l * 4096, e_b2 + l * 64,
            x_w1 + l * 4096, x_b1 + l * 64,
            x_w2 + l * 64, x_b2 + l,
            E);
        bool last = (l == 1);
        node_update_kernel<<<nodeBlocks, NT>>>(
            h_w1 + l * 128 * 64, h_b1 + l * 64,
            h_w2 + l * 4096, h_b2 + l * 64,
            last ? out : nullptr, last ? out + (size_t)N * 64 : nullptr, N);
    }
}

// round 6
// speedup vs baseline: 2.6631x; 1.1581x over previous
#include <cuda_runtime.h>
#include <cstdint>

#define NT 256          // node kernels: threads per block
#define TS 64           // node tile rows
#define LDA 68          // sA row stride (floats) for SIMT gemm
#define ET 128          // edge tile (edges per block)
#define LDE 68          // edge smem row stride (floats)

typedef unsigned long long u64;

__device__ float g_h [50048 * 64];
__device__ float g_x [50048 * 3];
__device__ float g_Ad[50048 * 64];   // h @ e_w1[0:64]   (dst part)
__device__ float g_As[50048 * 64];   // h @ e_w1[64:128] (src part)
__device__ float g_m [50048 * 64];   // segment-sum of m_ij
__device__ float g_dx[50048 * 3];    // segment-sum of W_ij * x_diff

__device__ __forceinline__ float silu_f(float v) {
    return v / (1.0f + __expf(-v));
}
__device__ __forceinline__ u64 pdup(float x) {
    u64 r; asm("mov.b64 %0, {%1, %1};" : "=l"(r) : "f"(x)); return r;
}
__device__ __forceinline__ void up2(u64 v, float& a, float& b) {
    asm("mov.b64 {%0, %1}, %2;" : "=f"(a), "=f"(b) : "l"(v));
}
__device__ __forceinline__ void fma2(u64& c, u64 a, u64 b) {
    asm("fma.rn.f32x2 %0, %1, %2, %0;" : "+l"(c) : "l"(a), "l"(b));
}
__device__ __forceinline__ void red_add_v4(float* p, float a, float b, float c, float d) {
    asm volatile("red.global.add.v4.f32 [%0], {%1, %2, %3, %4};"
                 :: "l"(p), "f"(a), "f"(b), "f"(c), "f"(d) : "memory");
}
__device__ __forceinline__ void red_add_v2(float* p, float a, float b) {
    asm volatile("red.global.add.v2.f32 [%0], {%1, %2};"
                 :: "l"(p), "f"(a), "f"(b) : "memory");
}
__device__ __forceinline__ float tf32f(float x) {
    uint32_t u; asm("cvt.rna.tf32.f32 %0, %1;" : "=r"(u) : "f"(x));
    return __uint_as_float(u);
}
// D(16x8,f32) += A(16x8,tf32,row) * B(8x8,tf32,col)
__device__ __forceinline__ void mma16n8k8(float c[4], const uint32_t a[4],
                                          uint32_t b0, uint32_t b1) {
    asm volatile(
        "mma.sync.aligned.m16n8k8.row.col.f32.tf32.tf32.f32 "
        "{%0,%1,%2,%3}, {%4,%5,%6,%7}, {%8,%9}, {%0,%1,%2,%3};"
        : "+f"(c[0]), "+f"(c[1]), "+f"(c[2]), "+f"(c[3])
        : "r"(a[0]), "r"(a[1]), "r"(a[2]), "r"(a[3]), "r"(b0), "r"(b1));
}

// ===================== SIMT gemm (node kernels, R4-proven) ==================
__device__ __forceinline__ void gemm_t(const float* __restrict__ sA,
                                       const float* __restrict__ sW,
                                       int tx, int ty, u64 acc[4][2]) {
    const float* aR = sA + ty * 4 * LDA;
    const float* bC = sW + tx * 4;
#pragma unroll
    for (int kb = 0; kb < 64; kb += 4) {
        float4 av[4];
#pragma unroll
        for (int i = 0; i < 4; i++)
            av[i] = *(const float4*)(aR + i * LDA + kb);
#pragma unroll
        for (int kk = 0; kk < 4; kk++) {
            ulonglong2 b = *(const ulonglong2*)(bC + (kb + kk) * 64);
#pragma unroll
            for (int i = 0; i < 4; i++) {
                float a = (kk == 0) ? av[i].x : (kk == 1) ? av[i].y
                        : (kk == 2) ? av[i].z : av[i].w;
                u64 aa = pdup(a);
                fma2(acc[i][0], aa, b.x);
                fma2(acc[i][1], aa, b.y);
            }
        }
    }
}

#define ZERO_ACC(acc)                             \
    _Pragma("unroll") for (int i_ = 0; i_ < 4; i_++) { (acc)[i_][0] = 0ull; (acc)[i_][1] = 0ull; }
#define UNPACK_ROW(acc_row, c)  \
    up2((acc_row)[0], (c)[0], (c)[1]); up2((acc_row)[1], (c)[2], (c)[3]);

// ---------------------------------------------------------------------------
__global__ void init_kernel(const int* __restrict__ an,
                            const float* __restrict__ pos,
                            const float* __restrict__ emb, int N) {
    int p = blockIdx.x * blockDim.x + threadIdx.x;
    int nh = N * 64;
    if (p < nh) {
        int n = p >> 6, j = p & 63;
        g_h[p] = emb[an[n] * 64 + j];
    } else if (p < nh + N * 3) {
        g_x[p - nh] = pos[p - nh];
    }
}

// ---------------------------------------------------------------------------
__global__ __launch_bounds__(NT)
void node_pre_kernel(const float* __restrict__ w1, int N) {
    __shared__ float sA[TS * LDA];
    __shared__ float sW[4096];
    int tid = threadIdx.x;
    int n0 = blockIdx.x * TS;
    int tx = tid & 15, ty = tid >> 4;

    for (int p = tid; p < TS * 16; p += NT) {
        int i = p >> 4, j = (p & 15) * 4;
        int n = n0 + i;
        float4 v = make_float4(0.f, 0.f, 0.f, 0.f);
        if (n < N) {
            v = *(const float4*)&g_h[n * 64 + j];
            *(float4*)&g_m[n * 64 + j] = make_float4(0.f, 0.f, 0.f, 0.f);
        }
        *(float4*)&sA[i * LDA + j] = v;
    }
    if (tid < TS * 3) {
        int idx = n0 * 3 + tid;
        if (idx < N * 3) g_dx[idx] = 0.f;
    }
    for (int p = tid; p < 1024; p += NT)
        *(float4*)&sW[p * 4] = *(const float4*)&w1[p * 4];
    __syncthreads();

    u64 acc[4][2];
    ZERO_ACC(acc);
    gemm_t(sA, sW, tx, ty, acc);

#pragma unroll
    for (int i = 0; i < 4; i++) {
        int n = n0 + ty * 4 + i;
        if (n < N) {
            float c[4];
            UNPACK_ROW(acc[i], c);
            *(float4*)&g_Ad[n * 64 + tx * 4] = make_float4(c[0], c[1], c[2], c[3]);
        }
    }
    __syncthreads();
    for (int p = tid; p < 1024; p += NT)
        *(float4*)&sW[p * 4] = *(const float4*)&w1[4096 + p * 4];
    __syncthreads();

    ZERO_ACC(acc);
    gemm_t(sA, sW, tx, ty, acc);

#pragma unroll
    for (int i = 0; i < 4; i++) {
        int n = n0 + ty * 4 + i;
        if (n < N) {
            float c[4];
            UNPACK_ROW(acc[i], c);
            *(float4*)&g_As[n * 64 + tx * 4] = make_float4(c[0], c[1], c[2], c[3]);
        }
    }
}

// ---------------------------------------------------------------------------
// Tensor (mma.sync tf32) edge kernel: 128 edges/block, 128 threads (4 warps).
// Each warp owns 32 edge rows: 2 m16 tiles x 8 n8 tiles x 8 k8 steps.
__global__ __launch_bounds__(128)
void edge_kernel_mma(const int* __restrict__ src, const int* __restrict__ dst,
                     const float* __restrict__ w1r, const float* __restrict__ b1,
                     const float* __restrict__ w2,  const float* __restrict__ b2,
                     const float* __restrict__ xw1, const float* __restrict__ xb1,
                     const float* __restrict__ xw2, const float* __restrict__ xb2,
                     int E) {
    extern __shared__ float dyn[];
    float* sA = dyn;                 // [ET][LDE]
    float* sB = dyn + ET * LDE;      // [64][LDE], reused w2 -> xw1
    __shared__ int   sdst[ET], ssrc[ET];
    __shared__ float sxd[ET * 3], sr[ET], sWe[ET];
    __shared__ float sw1r[64], sb1v[64], sb2v[64], sxb1[64], sxw2[64];

    int tid = threadIdx.x;
    int lane = tid & 31, warp = tid >> 5;
    int gr = lane >> 2, gc = lane & 3;
    int e0 = blockIdx.x * ET;
    int rbase = warp * 32;

    // per-edge metadata
    {
        int eg = e0 + tid;
        int s = 0, d = -1;
        float d0 = 0.f, d1 = 0.f, d2 = 0.f;
        if (eg < E) {
            s = src[eg]; d = dst[eg];
            d0 = g_x[s * 3 + 0] - g_x[d * 3 + 0];
            d1 = g_x[s * 3 + 1] - g_x[d * 3 + 1];
            d2 = g_x[s * 3 + 2] - g_x[d * 3 + 2];
        }
        ssrc[tid] = s; sdst[tid] = d;
        sxd[tid * 3 + 0] = d0; sxd[tid * 3 + 1] = d1; sxd[tid * 3 + 2] = d2;
        sr[tid] = sqrtf(d0 * d0 + d1 * d1 + d2 * d2);
    }
    if (tid < 64) {
        sw1r[tid] = w1r[tid]; sb1v[tid] = b1[tid]; sb2v[tid] = b2[tid];
        sxb1[tid] = xb1[tid]; sxw2[tid] = xw2[tid];
    }
    // w2 (k-major [64][64]) -> sB, tf32-rounded
    for (int p = tid; p < 4096; p += 128) {
        int k = p >> 6, n = p & 63;
        sB[k * LDE + n] = tf32f(w2[p]);
    }
    __syncthreads();

    // stage 1: t1 = silu(Ad[dst]+As[src]+r*w1r+b1) -> sA (tf32)
    for (int p = tid; p < ET * 16; p += 128) {
        int e = p >> 4, j = (p & 15) * 4;
        int d = sdst[e];
        int dd = d < 0 ? 0 : d;
        int s  = ssrc[e];
        float4 ad = *(const float4*)&g_Ad[dd * 64 + j];
        float4 as = *(const float4*)&g_As[s * 64 + j];
        float r = sr[e];
        float4 o;
        o.x = tf32f(silu_f(ad.x + as.x + r * sw1r[j + 0] + sb1v[j + 0]));
        o.y = tf32f(silu_f(ad.y + as.y + r * sw1r[j + 1] + sb1v[j + 1]));
        o.z = tf32f(silu_f(ad.z + as.z + r * sw1r[j + 2] + sb1v[j + 2]));
        o.w = tf32f(silu_f(ad.w + as.w + r * sw1r[j + 3] + sb1v[j + 3]));
        *(float4*)&sA[e * LDE + j] = o;
    }
    __syncthreads();

    float acc[2][8][4];
#pragma unroll
    for (int mt = 0; mt < 2; mt++)
#pragma unroll
        for (int nt = 0; nt < 8; nt++)
#pragma unroll
            for (int q = 0; q < 4; q++) acc[mt][nt][q] = 0.f;

    // GEMM1: D = t1 @ w2
#pragma unroll
    for (int k0 = 0; k0 < 64; k0 += 8) {
        uint32_t af[2][4];
#pragma unroll
        for (int mt = 0; mt < 2; mt++) {
            const float* ap = sA + (rbase + mt * 16 + gr) * LDE + k0 + gc;
            af[mt][0] = __float_as_uint(ap[0]);
            af[mt][1] = __float_as_uint(ap[8 * LDE]);
            af[mt][2] = __float_as_uint(ap[4]);
            af[mt][3] = __float_as_uint(ap[8 * LDE + 4]);
        }
#pragma unroll
        for (int nt = 0; nt < 8; nt++) {
            uint32_t b0 = __float_as_uint(sB[(k0 + gc) * LDE + nt * 8 + gr]);
            uint32_t b1 = __float_as_uint(sB[(k0 + gc + 4) * LDE + nt * 8 + gr]);
            mma16n8k8(acc[0][nt], af[0], b0, b1);
            mma16n8k8(acc[1][nt], af[1], b0, b1);
        }
    }
    __syncthreads();   // everyone done reading sA/sB

    // epilogue 1: m = silu(D + b2); scatter to g_m; store tf32(m) -> sA
#pragma unroll
    for (int mt = 0; mt < 2; mt++) {
        int ra = rbase + mt * 16 + gr, rb = ra + 8;
        int da = sdst[ra], db = sdst[rb];
#pragma unroll
        for (int nt = 0; nt < 8; nt++) {
            int col = nt * 8 + gc * 2;
            float m00 = silu_f(acc[mt][nt][0] + sb2v[col]);
            float m01 = silu_f(acc[mt][nt][1] + sb2v[col + 1]);
            float m10 = silu_f(acc[mt][nt][2] + sb2v[col]);
            float m11 = silu_f(acc[mt][nt][3] + sb2v[col + 1]);
            if (da >= 0) red_add_v2(&g_m[da * 64 + col], m00, m01);
            if (db >= 0) red_add_v2(&g_m[db * 64 + col], m10, m11);
            *(float2*)&sA[ra * LDE + col] = make_float2(tf32f(m00), tf32f(m01));
            *(float2*)&sA[rb * LDE + col] = make_float2(tf32f(m10), tf32f(m11));
        }
    }
    // xw1 -> sB
    for (int p = tid; p < 4096; p += 128) {
        int k = p >> 6, n = p & 63;
        sB[k * LDE + n] = tf32f(xw1[p]);
    }
    __syncthreads();

#pragma unroll
    for (int mt = 0; mt < 2; mt++)
#pragma unroll
        for (int nt = 0; nt < 8; nt++)
#pragma unroll
            for (int q = 0; q < 4; q++) acc[mt][nt][q] = 0.f;

    // GEMM2: D = m @ xw1
#pragma unroll
    for (int k0 = 0; k0 < 64; k0 += 8) {
        uint32_t af[2][4];
#pragma unroll
        for (int mt = 0; mt < 2; mt++) {
            const float* ap = sA + (rbase + mt * 16 + gr) * LDE + k0 + gc;
            af[mt][0] = __float_as_uint(ap[0]);
            af[mt][1] = __float_as_uint(ap[8 * LDE]);
            af[mt][2] = __float_as_uint(ap[4]);
            af[mt][3] = __float_as_uint(ap[8 * LDE + 4]);
        }
#pragma unroll
        for (int nt = 0; nt < 8; nt++) {
            uint32_t b0 = __float_as_uint(sB[(k0 + gc) * LDE + nt * 8 + gr]);
            uint32_t b1 = __float_as_uint(sB[(k0 + gc + 4) * LDE + nt * 8 + gr]);
            mma16n8k8(acc[0][nt], af[0], b0, b1);
            mma16n8k8(acc[1][nt], af[1], b0, b1);
        }
    }

    // epilogue 2: W = silu(D + xb1) . xw2 + xb2
    {
        float Wv[2][2] = {{0.f, 0.f}, {0.f, 0.f}};
#pragma unroll
        for (int mt = 0; mt < 2; mt++)
#pragma unroll
            for (int nt = 0; nt < 8; nt++) {
                int col = nt * 8 + gc * 2;
                Wv[mt][0] += silu_f(acc[mt][nt][0] + sxb1[col]) * sxw2[col]
                           + silu_f(acc[mt][nt][1] + sxb1[col + 1]) * sxw2[col + 1];
                Wv[mt][1] += silu_f(acc[mt][nt][2] + sxb1[col]) * sxw2[col]
                           + silu_f(acc[mt][nt][3] + sxb1[col + 1]) * sxw2[col + 1];
            }
#pragma unroll
        for (int off = 1; off <= 2; off <<= 1) {
            Wv[0][0] += __shfl_xor_sync(0xffffffffu, Wv[0][0], off);
            Wv[0][1] += __shfl_xor_sync(0xffffffffu, Wv[0][1], off);
            Wv[1][0] += __shfl_xor_sync(0xffffffffu, Wv[1][0], off);
            Wv[1][1] += __shfl_xor_sync(0xffffffffu, Wv[1][1], off);
        }
        if (gc == 0) {
            float xb2v = __ldg(xb2);
            sWe[rbase + gr]      = Wv[0][0] + xb2v;
            sWe[rbase + gr + 8]  = Wv[0][1] + xb2v;
            sWe[rbase + gr + 16] = Wv[1][0] + xb2v;
            sWe[rbase + gr + 24] = Wv[1][1] + xb2v;
        }
    }
    __syncthreads();

    for (int p = tid; p < ET * 3; p += 128) {
        int e = p / 3, cc = p - e * 3;
        int d = sdst[e];
        if (d >= 0) atomicAdd(&g_dx[d * 3 + cc], sWe[e] * sxd[e * 3 + cc]);
    }
}

#define EDGE_DYN_BYTES ((ET * LDE + 64 * LDE) * 4)

// ---------------------------------------------------------------------------
__global__ __launch_bounds__(NT)
void node_update_kernel(const float* __restrict__ hw1, const float* __restrict__ hb1,
                        const float* __restrict__ hw2, const float* __restrict__ hb2,
                        float* __restrict__ outh, float* __restrict__ outx, int N) {
    __shared__ float sA[TS * LDA];
    __shared__ float sW[4096];
    int tid = threadIdx.x;
    int n0 = blockIdx.x * TS;
    int tx = tid & 15, ty = tid >> 4;

    for (int p = tid; p < TS * 16; p += NT) {
        int i = p >> 4, j = (p & 15) * 4;
        int n = n0 + i;
        float4 v = make_float4(0.f, 0.f, 0.f, 0.f);
        if (n < N) v = *(const float4*)&g_h[n * 64 + j];
        *(float4*)&sA[i * LDA + j] = v;
    }
    for (int p = tid; p < 1024; p += NT)
        *(float4*)&sW[p * 4] = *(const float4*)&hw1[p * 4];
    __syncthreads();

    u64 acc[4][2];
    ZERO_ACC(acc);
    gemm_t(sA, sW, tx, ty, acc);
    __syncthreads();

    for (int p = tid; p < TS * 16; p += NT) {
        int i = p >> 4, j = (p & 15) * 4;
        int n = n0 + i;
        float4 v = make_float4(0.f, 0.f, 0.f, 0.f);
        if (n < N) v = *(const float4*)&g_m[n * 64 + j];
        *(float4*)&sA[i * LDA + j] = v;
    }
    for (int p = tid; p < 1024; p += NT)
        *(float4*)&sW[p * 4] = *(const float4*)&hw1[4096 + p * 4];
    __syncthreads();
    gemm_t(sA, sW, tx, ty, acc);
    __syncthreads();

#pragma unroll
    for (int i = 0; i < 4; i++) {
        int e = ty * 4 + i;
        float c[4];
        UNPACK_ROW(acc[i], c);
#pragma unroll
        for (int q = 0; q < 4; q++) c[q] = silu_f(c[q] + hb1[tx * 4 + q]);
        *(float4*)&sA[e * LDA + tx * 4] = make_float4(c[0], c[1], c[2], c[3]);
    }
    for (int p = tid; p < 1024; p += NT)
        *(float4*)&sW[p * 4] = *(const float4*)&hw2[p * 4];
    __syncthreads();

    ZERO_ACC(acc);
    gemm_t(sA, sW, tx, ty, acc);

    float* hdst = outh ? outh : g_h;
#pragma unroll
    for (int i = 0; i < 4; i++) {
        int n = n0 + ty * 4 + i;
        if (n < N) {
            float c[4];
            UNPACK_ROW(acc[i], c);
            float4 o = *(const float4*)&g_h[n * 64 + tx * 4];
            o.x += c[0] + hb2[tx * 4 + 0];
            o.y += c[1] + hb2[tx * 4 + 1];
            o.z += c[2] + hb2[tx * 4 + 2];
            o.w += c[3] + hb2[tx * 4 + 3];
            *(float4*)&hdst[n * 64 + tx * 4] = o;
        }
    }
    float* xdst = outx ? outx : g_x;
    if (tid < TS * 3) {
        int idx = n0 * 3 + tid;
        if (idx < N * 3) xdst[idx] = g_x[idx] + g_dx[idx];
    }
}

// ---------------------------------------------------------------------------
extern "C" void kernel_launch(void* const* d_in, const int* in_sizes, int n_in,
                              void* d_out, int out_size) {
    const int*   an   = (const int*)d_in[0];
    const float* pos  = (const float*)d_in[1];
    const int*   eidx = (const int*)d_in[2];
    // d_in[3] = edge_attr (unused by reference)
    const float* emb  = (const float*)d_in[4];
    const float* e_w1 = (const float*)d_in[5];
    const float* e_b1 = (const float*)d_in[6];
    const float* e_w2 = (const float*)d_in[7];
    const float* e_b2 = (const float*)d_in[8];
    const float* h_w1 = (const float*)d_in[9];
    const float* h_b1 = (const float*)d_in[10];
    const float* h_w2 = (const float*)d_in[11];
    const float* h_b2 = (const float*)d_in[12];
    const float* x_w1 = (const float*)d_in[13];
    const float* x_b1 = (const float*)d_in[14];
    const float* x_w2 = (const float*)d_in[15];
    const float* x_b2 = (const float*)d_in[16];

    int N = in_sizes[0];
    int E = in_sizes[2] / 2;
    float* out = (float*)d_out;

    static bool attr_done = false;
    if (!attr_done) {
        cudaFuncSetAttribute(edge_kernel_mma,
                             cudaFuncAttributeMaxDynamicSharedMemorySize,
                             EDGE_DYN_BYTES);
        attr_done = true;
    }

    int nodeBlocks = (N + TS - 1) / TS;
    int edgeBlocks = (E + ET - 1) / ET;
    int totBlocks  = (N * 67 + 255) / 256;

    init_kernel<<<totBlocks, 256>>>(an, pos, emb, N);

    for (int l = 0; l < 2; l++) {
        const float* ew1l = e_w1 + l * 129 * 64;
        node_pre_kernel<<<nodeBlocks, NT>>>(ew1l, N);
        edge_kernel_mma<<<edgeBlocks, 128, EDGE_DYN_BYTES>>>(
            eidx, eidx + E,
            ew1l + 128 * 64, e_b1 + l * 64,
            e_w2 + l * 4096, e_b2 + l * 64,
            x_w1 + l * 4096, x_b1 + l * 64,
            x_w2 + l * 64, x_b2 + l,
            E);
        bool last = (l == 1);
        node_update_kernel<<<nodeBlocks, NT>>>(
            h_w1 + l * 128 * 64, h_b1 + l * 64,
            h_w2 + l * 4096, h_b2 + l * 64,
            last ? out : nullptr, last ? out + (size_t)N * 64 : nullptr, N);
    }
}